// round 6
// baseline (speedup 1.0000x reference)
#include <cuda_runtime.h>

#define NTOT 32768
#define TPB  1024

// Soft-shrinkage gate: sigmoid(10(y-b)) + sigmoid(-10(y+b))
// With u = exp(-10y), E = exp(10b):  s1+s2 = (u^2 E + 2u + E)/((1+uE)(u+E))
__device__ __forceinline__ float gate_fn(float y, float E) {
    float a = -10.0f * y;
    a = fminf(fmaxf(a, -40.0f), 40.0f);
    float u  = __expf(a);
    float t1 = u * E;
    float num = fmaf(u, t1, fmaf(2.0f, u, E));
    float den = (t1 + 1.0f) * (u + E);
    return __fdividef(num, den);
}

// Edge path, analysis with deinterleaved input.
// y[m] = sum_j k[2j]*co[m+j-2] + k[2j+1]*ce[m+j-1], indices clipped to [0,H)
__device__ __noinline__ void ana_edge4_d(const float* __restrict__ ce,
                                         const float* __restrict__ co,
                                         const float* __restrict__ k8,
                                         int m0, int H, float* y) {
#pragma unroll
    for (int i = 0; i < 4; i++) {
        int m = m0 + i;
        float s = 0.0f;
#pragma unroll
        for (int j = 0; j < 4; j++) {
            int ie = m + j - 1;
            if (ie >= 0 && ie < H) s = fmaf(k8[2 * j + 1], ce[ie], s);
            int io = m + j - 2;
            if (io >= 0 && io < H) s = fmaf(k8[2 * j], co[io], s);
        }
        y[i] = s;
    }
}

// Edge path, synthesis: 8 outputs p0..p0+7 of group g (standard layout)
__device__ __noinline__ void syn_edge8(const float* __restrict__ sm,
                                       const float* __restrict__ kf,
                                       int g, int p0, int HS, float* o) {
    int H = 1 << HS;
#pragma unroll
    for (int i = 0; i < 8; i++) {
        int p = p0 + i, h = p >> 1, odd = p & 1;
        float s = 0.0f;
#pragma unroll
        for (int r = 0; r < 2; r++) {
            const float* c  = sm + ((2 * g + r) << HS);
            const float* k8 = kf + (2 * g + r) * 8;
            if (odd) {
#pragma unroll
                for (int t = 0; t < 4; t++) {
                    int m = h + 2 - t;
                    if (m >= 0 && m < H) s = fmaf(k8[2 * t], c[m], s);
                }
            } else {
#pragma unroll
                for (int t = 0; t < 4; t++) {
                    int m = h + 1 - t;
                    if (m >= 0 && m < H) s = fmaf(k8[2 * t + 1], c[m], s);
                }
            }
        }
        o[i] = s;
    }
}

// Analysis level LVL. Input: G=2^LVL channels, each channel g stored
// DEINTERLEAVED in [g*M, (g+1)*M): ce (even samples) first H=M/2, co next H.
// Output: 2G channels x H. If DEINT_OUT, each output channel written
// deinterleaved (for the next analysis stage); else standard (for synthesis).
template<int LVL, bool DEINT_OUT>
__device__ void analysis_stage(float* sm, const float* kfl, const float* Etl) {
    const int HS = 14 - LVL;     // log2 H
    const int MS = 15 - LVL;
    const int H  = 1 << HS;
    const int tid = threadIdx.x;
    float4 acc[8];
#pragma unroll
    for (int j = 0; j < 8; j++) {
        int q  = tid + j * TPB;
        int e0 = q << 2;                 // output linear index, mult of 4
        int ch = e0 >> HS;
        int m0 = e0 & (H - 1);           // mult of 4
        const float* ce = sm + ((ch >> 1) << MS);
        const float* co = ce + H;
        float4 K0 = *(const float4*)(kfl + ch * 8);      // k0..k3
        float4 K1 = *(const float4*)(kfl + ch * 8 + 4);  // k4..k7
        float y0, y1, y2, y3;
        if (m0 >= 4 && m0 <= H - 8) {
            float2 ceA = *(const float2*)(ce + m0 - 2);   // ce[m0-2], ce[m0-1]
            float4 ceB = *(const float4*)(ce + m0);       // ce[m0..m0+3]
            float2 ceC = *(const float2*)(ce + m0 + 4);   // ce[m0+4], ce[m0+5]
            float2 coA = *(const float2*)(co + m0 - 2);
            float4 coB = *(const float4*)(co + m0);
            float2 coC = *(const float2*)(co + m0 + 4);
            // y[m] = k1*ce[m-1]+k3*ce[m]+k5*ce[m+1]+k7*ce[m+2]
            //      + k0*co[m-2]+k2*co[m-1]+k4*co[m]+k6*co[m+1]
            y0 =      K0.y * ceA.y;
            y0 = fmaf(K0.w, ceB.x, y0); y0 = fmaf(K1.y, ceB.y, y0);
            y0 = fmaf(K1.w, ceB.z, y0); y0 = fmaf(K0.x, coA.x, y0);
            y0 = fmaf(K0.z, coA.y, y0); y0 = fmaf(K1.x, coB.x, y0);
            y0 = fmaf(K1.z, coB.y, y0);
            y1 =      K0.y * ceB.x;
            y1 = fmaf(K0.w, ceB.y, y1); y1 = fmaf(K1.y, ceB.z, y1);
            y1 = fmaf(K1.w, ceB.w, y1); y1 = fmaf(K0.x, coA.y, y1);
            y1 = fmaf(K0.z, coB.x, y1); y1 = fmaf(K1.x, coB.y, y1);
            y1 = fmaf(K1.z, coB.z, y1);
            y2 =      K0.y * ceB.y;
            y2 = fmaf(K0.w, ceB.z, y2); y2 = fmaf(K1.y, ceB.w, y2);
            y2 = fmaf(K1.w, ceC.x, y2); y2 = fmaf(K0.x, coB.x, y2);
            y2 = fmaf(K0.z, coB.y, y2); y2 = fmaf(K1.x, coB.z, y2);
            y2 = fmaf(K1.z, coB.w, y2);
            y3 =      K0.y * ceB.z;
            y3 = fmaf(K0.w, ceB.w, y3); y3 = fmaf(K1.y, ceC.x, y3);
            y3 = fmaf(K1.w, ceC.y, y3); y3 = fmaf(K0.x, coB.y, y3);
            y3 = fmaf(K0.z, coB.z, y3); y3 = fmaf(K1.x, coB.w, y3);
            y3 = fmaf(K1.z, coC.x, y3);
        } else {
            float yy[4];
            ana_edge4_d(ce, co, kfl + ch * 8, m0, H, yy);
            y0 = yy[0]; y1 = yy[1]; y2 = yy[2]; y3 = yy[3];
        }
        acc[j] = make_float4(y0, y1, y2, y3);
    }
    // Gate burst: 32 independent gates, MUFU latency hidden by ILP.
#pragma unroll
    for (int j = 0; j < 8; j++) {
        int ch = ((tid + j * TPB) << 2) >> HS;
        float E = Etl[ch];
        float4 a = acc[j];
        a.x *= gate_fn(a.x, E);
        a.y *= gate_fn(a.y, E);
        a.z *= gate_fn(a.z, E);
        a.w *= gate_fn(a.w, E);
        acc[j] = a;
    }
    __syncthreads();   // all reads done before in-place overwrite
#pragma unroll
    for (int j = 0; j < 8; j++) {
        int q  = tid + j * TPB;
        int e0 = q << 2;
        if (DEINT_OUT) {
            int m0   = e0 & (H - 1);
            int base = e0 - m0;          // ch * H
            int half = H >> 1;
            float4 a = acc[j];
            *(float2*)(sm + base + (m0 >> 1))        = make_float2(a.x, a.z);
            *(float2*)(sm + base + half + (m0 >> 1)) = make_float2(a.y, a.w);
        } else {
            *(float4*)(sm + e0) = acc[j];
        }
    }
    __syncthreads();
}

// Synthesis level LVL: 2G channels x H -> G channels x M=2H, standard layout,
// in place, 8 outputs per thread.
template<int LVL>
__device__ void synthesis_stage(float* sm, const float* kfl) {
    const int MS = 15 - LVL;
    const int HS = 14 - LVL;
    const int H  = 1 << HS;
    const int M  = 1 << MS;
    const int tid = threadIdx.x;
    float4 acc[8];
#pragma unroll
    for (int j = 0; j < 4; j++) {
        int q  = tid + j * TPB;
        int e0 = q << 3;                 // mult of 8
        int g  = e0 >> MS;
        int p0 = e0 & (M - 1);           // mult of 8
        int h0 = p0 >> 1;                // mult of 4
        float4 Ka = *(const float4*)(kfl + g * 16);       // K[2g][0..3]
        float4 Kb = *(const float4*)(kfl + g * 16 + 4);   // K[2g][4..7]
        float4 Kc = *(const float4*)(kfl + g * 16 + 8);   // K[2g+1][0..3]
        float4 Kd = *(const float4*)(kfl + g * 16 + 12);  // K[2g+1][4..7]
        float o[8];
        if (h0 >= 4 && h0 <= H - 8) {
            const float* c0 = sm + (g << MS) + h0;   // channel 2g
            const float* c1 = c0 + H;                // channel 2g+1
            // a_k = c0[h0-2+k], k=0..7
            float2 aA = *(const float2*)(c0 - 2);
            float4 aB = *(const float4*)(c0);
            float2 aC = *(const float2*)(c0 + 4);
            float2 bA = *(const float2*)(c1 - 2);
            float4 bB = *(const float4*)(c1);
            float2 bC = *(const float2*)(c1 + 4);
            float a_[8] = {aA.x, aA.y, aB.x, aB.y, aB.z, aB.w, aC.x, aC.y};
            float b_[8] = {bA.x, bA.y, bB.x, bB.y, bB.z, bB.w, bC.x, bC.y};
#pragma unroll
            for (int d = 0; d < 4; d++) {
                // even output p = p0+2d (h' = h0+d):
                float oe =      Ka.y * a_[d + 3];
                oe = fmaf(Ka.w, a_[d + 2], oe);
                oe = fmaf(Kb.y, a_[d + 1], oe);
                oe = fmaf(Kb.w, a_[d],     oe);
                oe = fmaf(Kc.y, b_[d + 3], oe);
                oe = fmaf(Kc.w, b_[d + 2], oe);
                oe = fmaf(Kd.y, b_[d + 1], oe);
                oe = fmaf(Kd.w, b_[d],     oe);
                // odd output p = p0+2d+1:
                float oo =      Ka.x * a_[d + 4];
                oo = fmaf(Ka.z, a_[d + 3], oo);
                oo = fmaf(Kb.x, a_[d + 2], oo);
                oo = fmaf(Kb.z, a_[d + 1], oo);
                oo = fmaf(Kc.x, b_[d + 4], oo);
                oo = fmaf(Kc.z, b_[d + 3], oo);
                oo = fmaf(Kd.x, b_[d + 2], oo);
                oo = fmaf(Kd.z, b_[d + 1], oo);
                o[2 * d]     = oe;
                o[2 * d + 1] = oo;
            }
        } else {
            syn_edge8(sm, kfl, g, p0, HS, o);
        }
        acc[2 * j]     = make_float4(o[0], o[1], o[2], o[3]);
        acc[2 * j + 1] = make_float4(o[4], o[5], o[6], o[7]);
    }
    __syncthreads();
#pragma unroll
    for (int j = 0; j < 4; j++) {
        int e0 = (tid + j * TPB) << 3;
        *(float4*)(sm + e0)     = acc[2 * j];
        *(float4*)(sm + e0 + 4) = acc[2 * j + 1];
    }
    __syncthreads();
}

// Table layout: level l kernels at KOFF(l), Et at EOFF(l).
#define KOFF(l) (((1 << ((l) + 1)) * 8) - 16)
#define EOFF(l) ((1 << ((l) + 1)) - 2)

__global__ void __launch_bounds__(TPB, 1)
wpt_kernel(const float* __restrict__ x,
           const float* __restrict__ k1, const float* __restrict__ k2,
           const float* __restrict__ k3, const float* __restrict__ k4,
           const float* __restrict__ k5,
           const float* __restrict__ b1, const float* __restrict__ b2,
           const float* __restrict__ b3, const float* __restrict__ b4,
           const float* __restrict__ b5,
           float* __restrict__ out)
{
    extern __shared__ float smem[];
    float* sm = smem;               // 32768 floats: the row
    float* kf = smem + NTOT;        // 496 floats: all filter tables
    float* Et = kf + 496;           // 62 floats: all exp(10b)
    const int tid = threadIdx.x;

    const float* xr   = x   + (size_t)blockIdx.x * NTOT;
    float*       orow = out + (size_t)blockIdx.x * NTOT;

    // load x deinterleaved: ce at [0, 16384), co at [16384, 32768)
#pragma unroll
    for (int i = tid; i < NTOT / 4; i += TPB) {
        float4 v = ((const float4*)xr)[i];
        ((float2*)sm)[i]              = make_float2(v.x, v.z);   // ce[2i], ce[2i+1]
        ((float2*)(sm + NTOT / 2))[i] = make_float2(v.y, v.w);   // co[2i], co[2i+1]
    }

    // preload all tables once
    if (tid < 496) {
        float v;
        if      (tid < 16)  v = k1[tid];
        else if (tid < 48)  v = k2[tid - 16];
        else if (tid < 112) v = k3[tid - 48];
        else if (tid < 240) v = k4[tid - 112];
        else                v = k5[tid - 240];
        kf[tid] = v;
    } else if (tid >= 512 && tid < 574) {
        int u = tid - 512;
        float bv;
        if      (u < 2)  bv = b1[u];
        else if (u < 6)  bv = b2[u - 2];
        else if (u < 14) bv = b3[u - 6];
        else if (u < 30) bv = b4[u - 14];
        else             bv = b5[u - 30];
        Et[u] = __expf(10.0f * bv);
    }
    __syncthreads();

    // ---- Analysis (deinterleaved in; deint out except last) ----
    analysis_stage<0, true >(sm, kf + KOFF(0), Et + EOFF(0));
    analysis_stage<1, true >(sm, kf + KOFF(1), Et + EOFF(1));
    analysis_stage<2, true >(sm, kf + KOFF(2), Et + EOFF(2));
    analysis_stage<3, true >(sm, kf + KOFF(3), Et + EOFF(3));
    analysis_stage<4, false>(sm, kf + KOFF(4), Et + EOFF(4));

    // ---- Synthesis (standard layout) ----
    synthesis_stage<4>(sm, kf + KOFF(4));
    synthesis_stage<3>(sm, kf + KOFF(3));
    synthesis_stage<2>(sm, kf + KOFF(2));
    synthesis_stage<1>(sm, kf + KOFF(1));
    synthesis_stage<0>(sm, kf + KOFF(0));

#pragma unroll
    for (int i = tid; i < NTOT / 4; i += TPB)
        ((float4*)orow)[i] = ((const float4*)sm)[i];
}

extern "C" void kernel_launch(void* const* d_in, const int* in_sizes, int n_in,
                              void* d_out, int out_size) {
    const float* x  = (const float*)d_in[0];
    const float* k1 = (const float*)d_in[1];
    const float* k2 = (const float*)d_in[2];
    const float* k3 = (const float*)d_in[3];
    const float* k4 = (const float*)d_in[4];
    const float* k5 = (const float*)d_in[5];
    const float* b1 = (const float*)d_in[6];
    const float* b2 = (const float*)d_in[7];
    const float* b3 = (const float*)d_in[8];
    const float* b4 = (const float*)d_in[9];
    const float* b5 = (const float*)d_in[10];
    float* out = (float*)d_out;

    int nrows = out_size / NTOT;   // 128
    size_t smem_bytes = (size_t)(NTOT + 496 + 62 + 32) * sizeof(float);
    cudaFuncSetAttribute(wpt_kernel, cudaFuncAttributeMaxDynamicSharedMemorySize,
                         (int)smem_bytes);
    wpt_kernel<<<nrows, TPB, smem_bytes>>>(x, k1, k2, k3, k4, k5,
                                           b1, b2, b3, b4, b5, out);
}

// round 8
// speedup vs baseline: 1.0998x; 1.0998x over previous
#include <cuda_runtime.h>

#define NTOT 32768
#define TPB  1024

// Soft-shrinkage gate: sigmoid(10(y-b)) + sigmoid(-10(y+b))
// With u = exp(-10y), E = exp(10b):  s1+s2 = (u^2 E + 2u + E)/((1+uE)(u+E))
__device__ __forceinline__ float gate_fn(float y, float E) {
    float a = -10.0f * y;
    a = fminf(fmaxf(a, -40.0f), 40.0f);
    float u  = __expf(a);
    float t1 = u * E;
    float num = fmaf(u, t1, fmaf(2.0f, u, E));
    float den = (t1 + 1.0f) * (u + E);
    return __fdividef(num, den);
}

// Edge path, analysis (interleaved layout): y[m]=sum_t K[t]*c[2m+t-3], clip [0,M)
__device__ __noinline__ void ana_edge4(const float* __restrict__ c,
                                       const float* __restrict__ k8,
                                       int m0, int M, float* y) {
#pragma unroll
    for (int i = 0; i < 4; i++) {
        float s = 0.0f;
#pragma unroll
        for (int t = 0; t < 8; t++) {
            int p = 2 * (m0 + i) + t - 3;
            if (p >= 0 && p < M) s = fmaf(k8[t], c[p], s);
        }
        y[i] = s;
    }
}

// Edge path, synthesis: 8 outputs p0..p0+7 of group g
__device__ __noinline__ void syn_edge8(const float* __restrict__ sm,
                                       const float* __restrict__ kf,
                                       int g, int p0, int HS, float* o) {
    int H = 1 << HS;
#pragma unroll
    for (int i = 0; i < 8; i++) {
        int p = p0 + i, h = p >> 1, odd = p & 1;
        float s = 0.0f;
#pragma unroll
        for (int r = 0; r < 2; r++) {
            const float* c  = sm + ((2 * g + r) << HS);
            const float* k8 = kf + (2 * g + r) * 8;
            if (odd) {
#pragma unroll
                for (int t = 0; t < 4; t++) {
                    int m = h + 2 - t;
                    if (m >= 0 && m < H) s = fmaf(k8[2 * t], c[m], s);
                }
            } else {
#pragma unroll
                for (int t = 0; t < 4; t++) {
                    int m = h + 1 - t;
                    if (m >= 0 && m < H) s = fmaf(k8[2 * t + 1], c[m], s);
                }
            }
        }
        o[i] = s;
    }
}

// One quad (4 outputs) of analysis level LVL, interleaved layout, gated.
template<int LVL>
__device__ __forceinline__ float4 ana_quad(const float* __restrict__ sm,
                                           const float* __restrict__ kfl,
                                           const float* __restrict__ Etl, int q) {
    const int HS = 14 - LVL;
    const int MS = 15 - LVL;
    const int H  = 1 << HS;
    const int M  = 1 << MS;
    int e0 = q << 2;
    int ch = e0 >> HS;
    int m0 = e0 & (H - 1);           // mult of 4
    const float* cb = sm + ((ch >> 1) << MS);
    float4 K0 = *(const float4*)(kfl + ch * 8);
    float4 K1 = *(const float4*)(kfl + ch * 8 + 4);
    float y0, y1, y2, y3;
    if (m0 >= 2 && m0 <= H - 6) {
        const float* pp = cb + (m0 << 1);          // 16B aligned
        float4 A  = *(const float4*)(pp - 4);      // c[2m0-4 .. 2m0-1]
        float4 Bv = *(const float4*)(pp);
        float4 Cv = *(const float4*)(pp + 4);
        float4 Dv = *(const float4*)(pp + 8);
        // w[u] = c[2m0-3+u];  A.y=w0 .. Dv.z=w13
        y0 =      K0.x * A.y;
        y0 = fmaf(K0.y, A.z,  y0);  y0 = fmaf(K0.z, A.w,  y0);
        y0 = fmaf(K0.w, Bv.x, y0);  y0 = fmaf(K1.x, Bv.y, y0);
        y0 = fmaf(K1.y, Bv.z, y0);  y0 = fmaf(K1.z, Bv.w, y0);
        y0 = fmaf(K1.w, Cv.x, y0);
        y1 =      K0.x * A.w;
        y1 = fmaf(K0.y, Bv.x, y1);  y1 = fmaf(K0.z, Bv.y, y1);
        y1 = fmaf(K0.w, Bv.z, y1);  y1 = fmaf(K1.x, Bv.w, y1);
        y1 = fmaf(K1.y, Cv.x, y1);  y1 = fmaf(K1.z, Cv.y, y1);
        y1 = fmaf(K1.w, Cv.z, y1);
        y2 =      K0.x * Bv.y;
        y2 = fmaf(K0.y, Bv.z, y2);  y2 = fmaf(K0.z, Bv.w, y2);
        y2 = fmaf(K0.w, Cv.x, y2);  y2 = fmaf(K1.x, Cv.y, y2);
        y2 = fmaf(K1.y, Cv.z, y2);  y2 = fmaf(K1.z, Cv.w, y2);
        y2 = fmaf(K1.w, Dv.x, y2);
        y3 =      K0.x * Bv.w;
        y3 = fmaf(K0.y, Cv.x, y3);  y3 = fmaf(K0.z, Cv.y, y3);
        y3 = fmaf(K0.w, Cv.z, y3);  y3 = fmaf(K1.x, Cv.w, y3);
        y3 = fmaf(K1.y, Dv.x, y3);  y3 = fmaf(K1.z, Dv.y, y3);
        y3 = fmaf(K1.w, Dv.z, y3);
    } else {
        float yy[4];
        ana_edge4(cb, kfl + ch * 8, m0, M, yy);
        y0 = yy[0]; y1 = yy[1]; y2 = yy[2]; y3 = yy[3];
    }
    float E = Etl[ch];
    return make_float4(y0 * gate_fn(y0, E), y1 * gate_fn(y1, E),
                       y2 * gate_fn(y2, E), y3 * gate_fn(y3, E));
}

// One oct (8 outputs) of synthesis level LVL.
template<int LVL>
__device__ __forceinline__ void syn_oct(const float* __restrict__ sm,
                                        const float* __restrict__ kfl,
                                        int q, float4& lo, float4& hi) {
    const int MS = 15 - LVL;
    const int HS = 14 - LVL;
    const int H  = 1 << HS;
    const int M  = 1 << MS;
    int e0 = q << 3;                 // mult of 8
    int g  = e0 >> MS;
    int p0 = e0 & (M - 1);           // mult of 8
    int h0 = p0 >> 1;                // mult of 4
    float4 Ka = *(const float4*)(kfl + g * 16);       // K[2g][0..3]
    float4 Kb = *(const float4*)(kfl + g * 16 + 4);   // K[2g][4..7]
    float4 Kc = *(const float4*)(kfl + g * 16 + 8);   // K[2g+1][0..3]
    float4 Kd = *(const float4*)(kfl + g * 16 + 12);  // K[2g+1][4..7]
    float o[8];
    if (h0 >= 4 && h0 <= H - 8) {
        const float* c0 = sm + (g << MS) + h0;   // channel 2g
        const float* c1 = c0 + H;                // channel 2g+1
        float2 aA = *(const float2*)(c0 - 2);
        float4 aB = *(const float4*)(c0);
        float2 aC = *(const float2*)(c0 + 4);
        float2 bA = *(const float2*)(c1 - 2);
        float4 bB = *(const float4*)(c1);
        float2 bC = *(const float2*)(c1 + 4);
        float a_[8] = {aA.x, aA.y, aB.x, aB.y, aB.z, aB.w, aC.x, aC.y};
        float b_[8] = {bA.x, bA.y, bB.x, bB.y, bB.z, bB.w, bC.x, bC.y};
#pragma unroll
        for (int d = 0; d < 4; d++) {
            float oe =      Ka.y * a_[d + 3];
            oe = fmaf(Ka.w, a_[d + 2], oe);
            oe = fmaf(Kb.y, a_[d + 1], oe);
            oe = fmaf(Kb.w, a_[d],     oe);
            oe = fmaf(Kc.y, b_[d + 3], oe);
            oe = fmaf(Kc.w, b_[d + 2], oe);
            oe = fmaf(Kd.y, b_[d + 1], oe);
            oe = fmaf(Kd.w, b_[d],     oe);
            float oo =      Ka.x * a_[d + 4];
            oo = fmaf(Ka.z, a_[d + 3], oo);
            oo = fmaf(Kb.x, a_[d + 2], oo);
            oo = fmaf(Kb.z, a_[d + 1], oo);
            oo = fmaf(Kc.x, b_[d + 4], oo);
            oo = fmaf(Kc.z, b_[d + 3], oo);
            oo = fmaf(Kd.x, b_[d + 2], oo);
            oo = fmaf(Kd.z, b_[d + 1], oo);
            o[2 * d]     = oe;
            o[2 * d + 1] = oo;
        }
    } else {
        syn_edge8(sm, kfl, g, p0, HS, o);
    }
    lo = make_float4(o[0], o[1], o[2], o[3]);
    hi = make_float4(o[4], o[5], o[6], o[7]);
}

// Analysis stage driver. LVL>=1: two-phase (half-row at a time, acc[4]),
// valid because outputs in half h read only inputs in half h (pair regions
// are M-aligned, M <= NTOT/2). LVL==0: single region spans the row -> full.
template<int LVL>
__device__ void analysis_stage(float* sm, const float* kfl, const float* Etl) {
    const int tid = threadIdx.x;
    if constexpr (LVL == 0) {
        float4 acc[8];
#pragma unroll
        for (int j = 0; j < 8; j++)
            acc[j] = ana_quad<LVL>(sm, kfl, Etl, tid + j * TPB);
        __syncthreads();
#pragma unroll
        for (int j = 0; j < 8; j++)
            *(float4*)(sm + ((tid + j * TPB) << 2)) = acc[j];
        __syncthreads();
    } else {
        float4 acc[4];
#pragma unroll
        for (int j = 0; j < 4; j++)
            acc[j] = ana_quad<LVL>(sm, kfl, Etl, tid + j * TPB);
        __syncthreads();
#pragma unroll
        for (int j = 0; j < 4; j++)
            *(float4*)(sm + ((tid + j * TPB) << 2)) = acc[j];
        // phase 1 reads only half 1 (disjoint from phase-0 writes), no barrier needed
#pragma unroll
        for (int j = 0; j < 4; j++)
            acc[j] = ana_quad<LVL>(sm, kfl, Etl, tid + (4 + j) * TPB);
        __syncthreads();
#pragma unroll
        for (int j = 0; j < 4; j++)
            *(float4*)(sm + ((tid + (4 + j) * TPB) << 2)) = acc[j];
        __syncthreads();
    }
}

template<int LVL>
__device__ void synthesis_stage(float* sm, const float* kfl) {
    const int tid = threadIdx.x;
    if constexpr (LVL == 0) {
        float4 acc[8];
#pragma unroll
        for (int j = 0; j < 4; j++)
            syn_oct<LVL>(sm, kfl, tid + j * TPB, acc[2 * j], acc[2 * j + 1]);
        __syncthreads();
#pragma unroll
        for (int j = 0; j < 4; j++) {
            int e0 = (tid + j * TPB) << 3;
            *(float4*)(sm + e0)     = acc[2 * j];
            *(float4*)(sm + e0 + 4) = acc[2 * j + 1];
        }
        __syncthreads();
    } else {
        float4 acc[4];
#pragma unroll
        for (int j = 0; j < 2; j++)
            syn_oct<LVL>(sm, kfl, tid + j * TPB, acc[2 * j], acc[2 * j + 1]);
        __syncthreads();
#pragma unroll
        for (int j = 0; j < 2; j++) {
            int e0 = (tid + j * TPB) << 3;
            *(float4*)(sm + e0)     = acc[2 * j];
            *(float4*)(sm + e0 + 4) = acc[2 * j + 1];
        }
#pragma unroll
        for (int j = 0; j < 2; j++)
            syn_oct<LVL>(sm, kfl, tid + (2 + j) * TPB, acc[2 * j], acc[2 * j + 1]);
        __syncthreads();
#pragma unroll
        for (int j = 0; j < 2; j++) {
            int e0 = (tid + (2 + j) * TPB) << 3;
            *(float4*)(sm + e0)     = acc[2 * j];
            *(float4*)(sm + e0 + 4) = acc[2 * j + 1];
        }
        __syncthreads();
    }
}

// Table layout: level l kernels at KOFF(l), Et at EOFF(l).
#define KOFF(l) (((1 << ((l) + 1)) * 8) - 16)
#define EOFF(l) ((1 << ((l) + 1)) - 2)

__global__ void __launch_bounds__(TPB, 1)
wpt_kernel(const float* __restrict__ x,
           const float* __restrict__ k1, const float* __restrict__ k2,
           const float* __restrict__ k3, const float* __restrict__ k4,
           const float* __restrict__ k5,
           const float* __restrict__ b1, const float* __restrict__ b2,
           const float* __restrict__ b3, const float* __restrict__ b4,
           const float* __restrict__ b5,
           float* __restrict__ out)
{
    extern __shared__ float smem[];
    float* sm = smem;               // 32768 floats: the row
    float* kf = smem + NTOT;        // 496 floats: all filter tables
    float* Et = kf + 496;           // 62 floats: all exp(10b)
    const int tid = threadIdx.x;

    const float* xr   = x   + (size_t)blockIdx.x * NTOT;
    float*       orow = out + (size_t)blockIdx.x * NTOT;

#pragma unroll
    for (int i = tid; i < NTOT / 4; i += TPB)
        ((float4*)sm)[i] = ((const float4*)xr)[i];

    // preload all tables once
    if (tid < 496) {
        float v;
        if      (tid < 16)  v = k1[tid];
        else if (tid < 48)  v = k2[tid - 16];
        else if (tid < 112) v = k3[tid - 48];
        else if (tid < 240) v = k4[tid - 112];
        else                v = k5[tid - 240];
        kf[tid] = v;
    } else if (tid >= 512 && tid < 574) {
        int u = tid - 512;
        float bv;
        if      (u < 2)  bv = b1[u];
        else if (u < 6)  bv = b2[u - 2];
        else if (u < 14) bv = b3[u - 6];
        else if (u < 30) bv = b4[u - 14];
        else             bv = b5[u - 30];
        Et[u] = __expf(10.0f * bv);
    }
    __syncthreads();

    // ---- Analysis ----
    analysis_stage<0>(sm, kf + KOFF(0), Et + EOFF(0));
    analysis_stage<1>(sm, kf + KOFF(1), Et + EOFF(1));
    analysis_stage<2>(sm, kf + KOFF(2), Et + EOFF(2));
    analysis_stage<3>(sm, kf + KOFF(3), Et + EOFF(3));
    analysis_stage<4>(sm, kf + KOFF(4), Et + EOFF(4));

    // ---- Synthesis ----
    synthesis_stage<4>(sm, kf + KOFF(4));
    synthesis_stage<3>(sm, kf + KOFF(3));
    synthesis_stage<2>(sm, kf + KOFF(2));
    synthesis_stage<1>(sm, kf + KOFF(1));
    synthesis_stage<0>(sm, kf + KOFF(0));

#pragma unroll
    for (int i = tid; i < NTOT / 4; i += TPB)
        ((float4*)orow)[i] = ((const float4*)sm)[i];
}

extern "C" void kernel_launch(void* const* d_in, const int* in_sizes, int n_in,
                              void* d_out, int out_size) {
    const float* x  = (const float*)d_in[0];
    const float* k1 = (const float*)d_in[1];
    const float* k2 = (const float*)d_in[2];
    const float* k3 = (const float*)d_in[3];
    const float* k4 = (const float*)d_in[4];
    const float* k5 = (const float*)d_in[5];
    const float* b1 = (const float*)d_in[6];
    const float* b2 = (const float*)d_in[7];
    const float* b3 = (const float*)d_in[8];
    const float* b4 = (const float*)d_in[9];
    const float* b5 = (const float*)d_in[10];
    float* out = (float*)d_out;

    int nrows = out_size / NTOT;   // 128
    size_t smem_bytes = (size_t)(NTOT + 496 + 62 + 32) * sizeof(float);
    cudaFuncSetAttribute(wpt_kernel, cudaFuncAttributeMaxDynamicSharedMemorySize,
                         (int)smem_bytes);
    wpt_kernel<<<nrows, TPB, smem_bytes>>>(x, k1, k2, k3, k4, k5,
                                           b1, b2, b3, b4, b5, out);
}

// round 10
// speedup vs baseline: 1.6548x; 1.5047x over previous
#include <cuda_runtime.h>

#define NTOT 32768
#define TPB  1024
#define GAP  12          // zero guard floats between regions
#define PRE  4           // floats before region 0

// Region base for layout with R regions of size S: base(r) = PRE + r*(S+GAP).

// Soft-shrinkage gate, exact evenness form (u = exp(-10|y|) <= 1, no overflow):
//   gate = (u^2 E + 2u + E)/((1+uE)(u+E)),  E = exp(10b) in [1, e]
// returns y * gate.
__device__ __forceinline__ float gate_mul(float y, float E) {
    float u  = __expf(-10.0f * fabsf(y));   // <= 1, never overflows
    float t1 = u * E;
    float num = fmaf(u, t1, fmaf(2.0f, u, E));   // u^2 E + 2u + E
    float den = (t1 + 1.0f) * (u + E);
    return __fdividef(y * num, den);
}

// Analysis level LVL: 2^LVL regions x M -> 2^(LVL+1) regions x H=M/2, in place.
// Guard zeros make the main path valid for every m0 (no edge branch).
template<int LVL>
__device__ void analysis_stage(float* __restrict__ sm,
                               const float* __restrict__ kfl,
                               const float* __restrict__ Etl) {
    const int HS = 14 - LVL;     // log2 H
    const int MS = 15 - LVL;     // log2 M
    const int H  = 1 << HS;
    const int Rout = 2 << LVL;
    const int tid = threadIdx.x;
    float4 acc[8];
#pragma unroll
    for (int j = 0; j < 8; j++) {
        int q  = tid + j * TPB;
        int e0 = q << 2;                 // output linear index, mult of 4
        int ch = e0 >> HS;
        int m0 = e0 & (H - 1);           // mult of 4
        int g  = ch >> 1;
        const float* cb = sm + (g << MS) + GAP * g + PRE;  // input region g
        float4 K0 = *(const float4*)(kfl + ch * 8);        // k0..k3
        float4 K1 = *(const float4*)(kfl + ch * 8 + 4);    // k4..k7
        const float* pp = cb + (m0 << 1);          // 16B aligned
        float4 A  = *(const float4*)(pp - 4);      // c[2m0-4 .. 2m0-1]
        float4 Bv = *(const float4*)(pp);
        float4 Cv = *(const float4*)(pp + 4);
        float4 Dv = *(const float4*)(pp + 8);
        // w[u] = c[2m0-3+u];  A.y=w0 .. Dv.z=w13; y_i = sum_t K[t]*w[t+2i]
        float y0, y1, y2, y3;
        y0 =      K0.x * A.y;
        y0 = fmaf(K0.y, A.z,  y0);  y0 = fmaf(K0.z, A.w,  y0);
        y0 = fmaf(K0.w, Bv.x, y0);  y0 = fmaf(K1.x, Bv.y, y0);
        y0 = fmaf(K1.y, Bv.z, y0);  y0 = fmaf(K1.z, Bv.w, y0);
        y0 = fmaf(K1.w, Cv.x, y0);
        y1 =      K0.x * A.w;
        y1 = fmaf(K0.y, Bv.x, y1);  y1 = fmaf(K0.z, Bv.y, y1);
        y1 = fmaf(K0.w, Bv.z, y1);  y1 = fmaf(K1.x, Bv.w, y1);
        y1 = fmaf(K1.y, Cv.x, y1);  y1 = fmaf(K1.z, Cv.y, y1);
        y1 = fmaf(K1.w, Cv.z, y1);
        y2 =      K0.x * Bv.y;
        y2 = fmaf(K0.y, Bv.z, y2);  y2 = fmaf(K0.z, Bv.w, y2);
        y2 = fmaf(K0.w, Cv.x, y2);  y2 = fmaf(K1.x, Cv.y, y2);
        y2 = fmaf(K1.y, Cv.z, y2);  y2 = fmaf(K1.z, Cv.w, y2);
        y2 = fmaf(K1.w, Dv.x, y2);
        y3 =      K0.x * Bv.w;
        y3 = fmaf(K0.y, Cv.x, y3);  y3 = fmaf(K0.z, Cv.y, y3);
        y3 = fmaf(K0.w, Cv.z, y3);  y3 = fmaf(K1.x, Cv.w, y3);
        y3 = fmaf(K1.y, Dv.x, y3);  y3 = fmaf(K1.z, Dv.y, y3);
        y3 = fmaf(K1.w, Dv.z, y3);
        float E = Etl[ch];
        acc[j] = make_float4(gate_mul(y0, E), gate_mul(y1, E),
                             gate_mul(y2, E), gate_mul(y3, E));
    }
    __syncthreads();   // all reads done before in-place overwrite
#pragma unroll
    for (int j = 0; j < 8; j++) {
        int q  = tid + j * TPB;
        int e0 = q << 2;
        int ch = e0 >> HS;
        *(float4*)(sm + e0 + GAP * ch + PRE) = acc[j];
    }
    // zero guards for the OUTPUT layout (Rout regions of H)
    if (tid < PRE) {
        sm[tid] = 0.0f;
    } else if (tid >= 32 && tid < 32 + GAP * Rout) {
        int u = tid - 32;
        int r = u / GAP + 1, off = u % GAP;
        sm[r * (H + GAP) + PRE - GAP + off] = 0.0f;
    }
    __syncthreads();
}

// Synthesis level LVL: 2^(LVL+1) regions x H -> 2^LVL regions x M=2H, in place.
// Guard zeros -> main path valid for every h0.
template<int LVL>
__device__ void synthesis_stage(float* __restrict__ sm,
                                const float* __restrict__ kfl) {
    const int MS = 15 - LVL;
    const int HS = 14 - LVL;
    const int H  = 1 << HS;
    const int M  = 1 << MS;
    const int Rout = 1 << LVL;
    const int tid = threadIdx.x;
    float4 acc[8];
#pragma unroll
    for (int j = 0; j < 8; j++) {
        int q  = tid + j * TPB;
        int e0 = q << 2;
        int g  = e0 >> MS;
        int p0 = e0 & (M - 1);           // mult of 4
        int h0 = p0 >> 1;                // mult of 2
        const float* c0 = sm + (g << MS) + 2 * GAP * g + PRE + h0;  // channel 2g
        const float* c1 = c0 + H + GAP;                             // channel 2g+1
        float4 Ka = *(const float4*)(kfl + g * 16);       // K[2g][0..3]
        float4 Kb = *(const float4*)(kfl + g * 16 + 4);   // K[2g][4..7]
        float4 Kc = *(const float4*)(kfl + g * 16 + 8);   // K[2g+1][0..3]
        float4 Kd = *(const float4*)(kfl + g * 16 + 12);  // K[2g+1][4..7]
        float2 aA = *(const float2*)(c0 - 2);    // a0=c0[h0-2], a1
        float2 aB = *(const float2*)(c0);        // a2, a3
        float2 aC = *(const float2*)(c0 + 2);    // a4, a5
        float2 bA = *(const float2*)(c1 - 2);
        float2 bB = *(const float2*)(c1);
        float2 bC = *(const float2*)(c1 + 2);
        // even p (h'=h0+d): k1*a[d+3]+k3*a[d+2]+k5*a[d+1]+k7*a[d]  (+ channel 2g+1)
        // odd  p:           k0*a[d+4]+k2*a[d+3]+k4*a[d+2]+k6*a[d+1]
        float o0, o1, o2, o3;
        o0 =      Ka.y * aB.y;
        o0 = fmaf(Ka.w, aB.x, o0);  o0 = fmaf(Kb.y, aA.y, o0);
        o0 = fmaf(Kb.w, aA.x, o0);  o0 = fmaf(Kc.y, bB.y, o0);
        o0 = fmaf(Kc.w, bB.x, o0);  o0 = fmaf(Kd.y, bA.y, o0);
        o0 = fmaf(Kd.w, bA.x, o0);
        o1 =      Ka.x * aC.x;
        o1 = fmaf(Ka.z, aB.y, o1);  o1 = fmaf(Kb.x, aB.x, o1);
        o1 = fmaf(Kb.z, aA.y, o1);  o1 = fmaf(Kc.x, bC.x, o1);
        o1 = fmaf(Kc.z, bB.y, o1);  o1 = fmaf(Kd.x, bB.x, o1);
        o1 = fmaf(Kd.z, bA.y, o1);
        o2 =      Ka.y * aC.x;
        o2 = fmaf(Ka.w, aB.y, o2);  o2 = fmaf(Kb.y, aB.x, o2);
        o2 = fmaf(Kb.w, aA.y, o2);  o2 = fmaf(Kc.y, bC.x, o2);
        o2 = fmaf(Kc.w, bB.y, o2);  o2 = fmaf(Kd.y, bB.x, o2);
        o2 = fmaf(Kd.w, bA.y, o2);
        o3 =      Ka.x * aC.y;
        o3 = fmaf(Ka.z, aC.x, o3);  o3 = fmaf(Kb.x, aB.y, o3);
        o3 = fmaf(Kb.z, aB.x, o3);  o3 = fmaf(Kc.x, bC.y, o3);
        o3 = fmaf(Kc.z, bC.x, o3);  o3 = fmaf(Kd.x, bB.y, o3);
        o3 = fmaf(Kd.z, bB.x, o3);
        acc[j] = make_float4(o0, o1, o2, o3);
    }
    __syncthreads();
#pragma unroll
    for (int j = 0; j < 8; j++) {
        int q  = tid + j * TPB;
        int e0 = q << 2;
        int g  = e0 >> MS;
        *(float4*)(sm + e0 + GAP * g + PRE) = acc[j];
    }
    // zero guards for the OUTPUT layout (Rout regions of M)
    if (tid < PRE) {
        sm[tid] = 0.0f;
    } else if (tid >= 32 && tid < 32 + GAP * Rout) {
        int u = tid - 32;
        int r = u / GAP + 1, off = u % GAP;
        sm[r * (M + GAP) + PRE - GAP + off] = 0.0f;
    }
    __syncthreads();
}

// Table layout: level l kernels at KOFF(l), Et at EOFF(l).
#define KOFF(l) (((1 << ((l) + 1)) * 8) - 16)
#define EOFF(l) ((1 << ((l) + 1)) - 2)
#define DATA_FLOATS (NTOT + 512)     // row data incl. guards (max 4+32*1036 = 33156)

__global__ void __launch_bounds__(TPB, 1)
wpt_kernel(const float* __restrict__ x,
           const float* __restrict__ k1, const float* __restrict__ k2,
           const float* __restrict__ k3, const float* __restrict__ k4,
           const float* __restrict__ k5,
           const float* __restrict__ b1, const float* __restrict__ b2,
           const float* __restrict__ b3, const float* __restrict__ b4,
           const float* __restrict__ b5,
           float* __restrict__ out)
{
    extern __shared__ float smem[];
    float* sm = smem;                    // guarded row data
    float* kf = smem + DATA_FLOATS;      // 496 floats: all filter tables
    float* Et = kf + 496;                // 62 floats: all exp(10b)
    const int tid = threadIdx.x;

    const float* xr   = x   + (size_t)blockIdx.x * NTOT;
    float*       orow = out + (size_t)blockIdx.x * NTOT;

    // load x into region 0 (base PRE=4, 16B aligned)
#pragma unroll
    for (int i = tid; i < NTOT / 4; i += TPB)
        ((float4*)(sm + PRE))[i] = ((const float4*)xr)[i];
    // initial guards: [0,4) and [NTOT+4, NTOT+16)
    if (tid < PRE) sm[tid] = 0.0f;
    else if (tid >= 4 && tid < 16) sm[NTOT + tid] = 0.0f;

    // preload all tables once
    if (tid >= 512 && tid < 512 + 496) {
        int u = tid - 512;
        float v;
        if      (u < 16)  v = k1[u];
        else if (u < 48)  v = k2[u - 16];
        else if (u < 112) v = k3[u - 48];
        else if (u < 240) v = k4[u - 112];
        else              v = k5[u - 240];
        kf[u] = v;
    } else if (tid >= 256 && tid < 256 + 62) {
        int u = tid - 256;
        float bv;
        if      (u < 2)  bv = b1[u];
        else if (u < 6)  bv = b2[u - 2];
        else if (u < 14) bv = b3[u - 6];
        else if (u < 30) bv = b4[u - 14];
        else             bv = b5[u - 30];
        Et[u] = __expf(10.0f * bv);
    }
    __syncthreads();

    // ---- Analysis ----
    analysis_stage<0>(sm, kf + KOFF(0), Et + EOFF(0));
    analysis_stage<1>(sm, kf + KOFF(1), Et + EOFF(1));
    analysis_stage<2>(sm, kf + KOFF(2), Et + EOFF(2));
    analysis_stage<3>(sm, kf + KOFF(3), Et + EOFF(3));
    analysis_stage<4>(sm, kf + KOFF(4), Et + EOFF(4));

    // ---- Synthesis ----
    synthesis_stage<4>(sm, kf + KOFF(4));
    synthesis_stage<3>(sm, kf + KOFF(3));
    synthesis_stage<2>(sm, kf + KOFF(2));
    synthesis_stage<1>(sm, kf + KOFF(1));
    synthesis_stage<0>(sm, kf + KOFF(0));

#pragma unroll
    for (int i = tid; i < NTOT / 4; i += TPB)
        ((float4*)orow)[i] = ((const float4*)(sm + PRE))[i];
}

extern "C" void kernel_launch(void* const* d_in, const int* in_sizes, int n_in,
                              void* d_out, int out_size) {
    const float* x  = (const float*)d_in[0];
    const float* k1 = (const float*)d_in[1];
    const float* k2 = (const float*)d_in[2];
    const float* k3 = (const float*)d_in[3];
    const float* k4 = (const float*)d_in[4];
    const float* k5 = (const float*)d_in[5];
    const float* b1 = (const float*)d_in[6];
    const float* b2 = (const float*)d_in[7];
    const float* b3 = (const float*)d_in[8];
    const float* b4 = (const float*)d_in[9];
    const float* b5 = (const float*)d_in[10];
    float* out = (float*)d_out;

    int nrows = out_size / NTOT;   // 128
    size_t smem_bytes = (size_t)(DATA_FLOATS + 496 + 62 + 32) * sizeof(float);
    cudaFuncSetAttribute(wpt_kernel, cudaFuncAttributeMaxDynamicSharedMemorySize,
                         (int)smem_bytes);
    wpt_kernel<<<nrows, TPB, smem_bytes>>>(x, k1, k2, k3, k4, k5,
                                           b1, b2, b3, b4, b5, out);
}